// round 3
// baseline (speedup 1.0000x reference)
#include <cuda_runtime.h>

#define NMAX 4096

static constexpr float R_      = 0.1f;
static constexpr float DT_     = 1.0f / 60.0f;
static constexpr float MAXV    = 3.0f;                 // 0.5*0.1/DT
static constexpr float RHO0    = 17510.1f;
static constexpr float STIFF   = 2.99e-11f;
static constexpr float SPIKY   = 4.774648292756860e6f; // 15/(pi*R^6)
static constexpr float NSPIKY3 = -3.0f * 4.774648292756860e6f;
static constexpr float VDTR    = 60.0f * (1.0f / 60.0f) / 17510.1f; // VISC*DT/RHO0
static constexpr float EPS_    = 1e-8f;

// Scratch (device globals: no allocation, guard-safe)
__device__ float4 g_pA[NMAX];
__device__ float4 g_pB[NMAX];
__device__ float  g_lam[NMAX];
__device__ float4 g_nv[NMAX];

// ---------------------------------------------------------------------------
// 1) external forces + velocity cap + predicted positions
// ---------------------------------------------------------------------------
__global__ void k_predict(const float* __restrict__ locs,
                          const float* __restrict__ vel, int N) {
    int i = blockIdx.x * blockDim.x + threadIdx.x;
    if (i >= N) return;
    float vx = vel[3 * i + 0];
    float vy = vel[3 * i + 1] - 9.8f * DT_;
    float vz = vel[3 * i + 2];
    float nrm = sqrtf(vx * vx + vy * vy + vz * vz);
    float s = fminf(MAXV / (nrm + 1e-4f), 1.0f);
    vx *= s; vy *= s; vz *= s;
    g_pA[i] = make_float4(locs[3 * i + 0] + DT_ * vx,
                          locs[3 * i + 1] + DT_ * vy,
                          locs[3 * i + 2] + DT_ * vz, 0.0f);
}

// ---------------------------------------------------------------------------
// 2) lambda pass: rho_i = sum_j w_ij ; lam_i = -(rho-RHO0)*STIFF
//    warp-per-particle, all positions in SMEM (SoA, conflict-free)
// ---------------------------------------------------------------------------
__global__ void k_lambda(int srcA, int N) {
    extern __shared__ float sm[];
    float* xs = sm;
    float* ys = sm + NMAX;
    float* zs = sm + 2 * NMAX;
    const float4* __restrict__ src = srcA ? g_pA : g_pB;

    for (int k = threadIdx.x; k < N; k += blockDim.x) {
        float4 p = src[k];
        xs[k] = p.x; ys[k] = p.y; zs[k] = p.z;
    }
    __syncthreads();

    int w    = (blockIdx.x * blockDim.x + threadIdx.x) >> 5;
    int lane = threadIdx.x & 31;
    if (w >= N) return;

    float px = xs[w], py = ys[w], pz = zs[w];
    float rho = 0.0f;
#pragma unroll 4
    for (int j = lane; j < N; j += 32) {
        float dx = px - xs[j];
        float dy = py - ys[j];
        float dz = pz - zs[j];
        float d2 = dx * dx + dy * dy + dz * dz;
        float d2p = d2 + EPS_;
        float rinv = rsqrtf(d2p);
        float d = d2p * rinv;
        float t = (d < R_ && d2 > 1e-12f) ? (R_ - d) : 0.0f;
        rho += (SPIKY * t) * (t * t);
    }
#pragma unroll
    for (int o = 16; o; o >>= 1) rho += __shfl_xor_sync(0xffffffffu, rho, o);
    if (lane == 0) g_lam[w] = -(rho - RHO0) * STIFF;
}

// ---------------------------------------------------------------------------
// 3) delta pass: pred_i += sum_j (lam_i+lam_j) * dw_ij / d * (p_i - p_j)
//    lam[j] via __ldg (16KB, L1-resident)
// ---------------------------------------------------------------------------
__global__ void k_delta(int srcA, int N) {
    extern __shared__ float sm[];
    float* xs = sm;
    float* ys = sm + NMAX;
    float* zs = sm + 2 * NMAX;
    const float4* __restrict__ src = srcA ? g_pA : g_pB;
    float4* __restrict__ dst       = srcA ? g_pB : g_pA;

    for (int k = threadIdx.x; k < N; k += blockDim.x) {
        float4 p = src[k];
        xs[k] = p.x; ys[k] = p.y; zs[k] = p.z;
    }
    __syncthreads();

    int w    = (blockIdx.x * blockDim.x + threadIdx.x) >> 5;
    int lane = threadIdx.x & 31;
    if (w >= N) return;

    float px = xs[w], py = ys[w], pz = zs[w];
    float li = __ldg(&g_lam[w]);
    float ax = 0.0f, ay = 0.0f, az = 0.0f;
#pragma unroll 4
    for (int j = lane; j < N; j += 32) {
        float dx = px - xs[j];
        float dy = py - ys[j];
        float dz = pz - zs[j];
        float d2 = dx * dx + dy * dy + dz * dz;
        float d2p = d2 + EPS_;
        float rinv = rsqrtf(d2p);
        float d = d2p * rinv;
        float t = (d < R_ && d2 > 1e-12f) ? (R_ - d) : 0.0f;
        float lj = __ldg(&g_lam[j]);
        float coef = (li + lj) * (NSPIKY3 * (t * t)) * rinv;
        ax += coef * dx;
        ay += coef * dy;
        az += coef * dz;
    }
#pragma unroll
    for (int o = 16; o; o >>= 1) {
        ax += __shfl_xor_sync(0xffffffffu, ax, o);
        ay += __shfl_xor_sync(0xffffffffu, ay, o);
        az += __shfl_xor_sync(0xffffffffu, az, o);
    }
    if (lane == 0)
        dst[w] = make_float4(px + ax, py + ay, pz + az, 0.0f);
}

// ---------------------------------------------------------------------------
// 4) new_vel = (pred - locs)/DT ; also emit pred to output
// ---------------------------------------------------------------------------
__global__ void k_nvout(const float* __restrict__ locs,
                        float* __restrict__ out, int N) {
    int i = blockIdx.x * blockDim.x + threadIdx.x;
    if (i >= N) return;
    float4 p = g_pB[i];  // final pred after 3 ping-pong iters (A->B, B->A, A->B)
    float nx = (p.x - locs[3 * i + 0]) * (1.0f / DT_);
    float ny = (p.y - locs[3 * i + 1]) * (1.0f / DT_);
    float nz = (p.z - locs[3 * i + 2]) * (1.0f / DT_);
    g_nv[i] = make_float4(nx, ny, nz, 0.0f);
    out[3 * i + 0] = p.x;
    out[3 * i + 1] = p.y;
    out[3 * i + 2] = p.z;
}

// ---------------------------------------------------------------------------
// 5) XSPH viscosity: dv_i = sum_j w_ij (v_j - v_i); cap; emit new_vel
//    positions in SMEM, v_j via __ldg float4 (64KB, L1-resident)
// ---------------------------------------------------------------------------
__global__ void k_xsph(float* __restrict__ out, int N) {
    extern __shared__ float sm[];
    float* xs = sm;
    float* ys = sm + NMAX;
    float* zs = sm + 2 * NMAX;
    for (int k = threadIdx.x; k < N; k += blockDim.x) {
        float4 p = g_pB[k];
        xs[k] = p.x; ys[k] = p.y; zs[k] = p.z;
    }
    __syncthreads();

    int w    = (blockIdx.x * blockDim.x + threadIdx.x) >> 5;
    int lane = threadIdx.x & 31;
    if (w >= N) return;

    float px = xs[w], py = ys[w], pz = zs[w];
    float4 vi = __ldg(&g_nv[w]);
    float sx = 0.0f, sy = 0.0f, sz = 0.0f;
#pragma unroll 4
    for (int j = lane; j < N; j += 32) {
        float dx = px - xs[j];
        float dy = py - ys[j];
        float dz = pz - zs[j];
        float d2 = dx * dx + dy * dy + dz * dz;
        float d2p = d2 + EPS_;
        float rinv = rsqrtf(d2p);
        float d = d2p * rinv;
        float t = (d < R_ && d2 > 1e-12f) ? (R_ - d) : 0.0f;
        float wk = (SPIKY * t) * (t * t);
        float4 vj = __ldg(&g_nv[j]);
        sx += wk * (vj.x - vi.x);
        sy += wk * (vj.y - vi.y);
        sz += wk * (vj.z - vi.z);
    }
#pragma unroll
    for (int o = 16; o; o >>= 1) {
        sx += __shfl_xor_sync(0xffffffffu, sx, o);
        sy += __shfl_xor_sync(0xffffffffu, sy, o);
        sz += __shfl_xor_sync(0xffffffffu, sz, o);
    }
    if (lane == 0) {
        float nx = vi.x + VDTR * sx;
        float ny = vi.y + VDTR * sy;
        float nz = vi.z + VDTR * sz;
        float nrm = sqrtf(nx * nx + ny * ny + nz * nz);
        float s = fminf(MAXV / (nrm + 1e-4f), 1.0f);
        out[3 * N + 3 * w + 0] = nx * s;
        out[3 * N + 3 * w + 1] = ny * s;
        out[3 * N + 3 * w + 2] = nz * s;
    }
}

// ---------------------------------------------------------------------------
extern "C" void kernel_launch(void* const* d_in, const int* in_sizes, int n_in,
                              void* d_out, int out_size) {
    const float* locs = (const float*)d_in[0];
    const float* vel  = (const float*)d_in[1];
    float* out = (float*)d_out;
    int N = in_sizes[0] / 3;  // 4096

    const int TPB = 256;
    int eb = (N + TPB - 1) / TPB;                 // elementwise blocks
    int pb = (N * 32 + TPB - 1) / TPB;            // warp-per-particle blocks
    size_t sm3 = (size_t)3 * NMAX * sizeof(float);  // 48KB = default dyn-smem cap

    k_predict<<<eb, TPB>>>(locs, vel, N);
    int srcA = 1;
    for (int it = 0; it < 3; ++it) {
        k_lambda<<<pb, TPB, sm3>>>(srcA, N);
        k_delta<<<pb, TPB, sm3>>>(srcA, N);
        srcA ^= 1;
    }
    k_nvout<<<eb, TPB>>>(locs, out, N);
    k_xsph<<<pb, TPB, sm3>>>(out, N);
}

// round 5
// speedup vs baseline: 1.5383x; 1.5383x over previous
#include <cuda_runtime.h>

#define NMAX 4096

static constexpr float R_      = 0.1f;
static constexpr float DT_     = 1.0f / 60.0f;
static constexpr float MAXV    = 3.0f;                 // 0.5*0.1/DT
static constexpr float RHO0    = 17510.1f;
static constexpr float STIFF   = 2.99e-11f;
static constexpr float SPIKY   = 4.774648292756860e6f; // 15/(pi*R^6)
static constexpr float NSPIKY3 = -3.0f * 4.774648292756860e6f;
static constexpr float VDTR    = 60.0f * (1.0f / 60.0f) / 17510.1f; // VISC*DT/RHO0
static constexpr float EPS_    = 1e-8f;
// self-pair contribution to rho: d_self = sqrt(EPS) = 1e-4, t = R - 1e-4
static constexpr float W_SELF  =
    (float)(4.774648292756860e6 * 0.0999 * 0.0999 * 0.0999);

// ---------------- packed f32x2 helpers (Blackwell-only FFMA2/FADD2/FMUL2) ----
__device__ __forceinline__ float2 pkadd(float2 a, float2 b) {
    float2 r;
    asm("{\n\t.reg .b64 a64, b64, r64;\n\t"
        "mov.b64 a64, {%2, %3};\n\t"
        "mov.b64 b64, {%4, %5};\n\t"
        "add.rn.f32x2 r64, a64, b64;\n\t"
        "mov.b64 {%0, %1}, r64;\n\t}"
        : "=f"(r.x), "=f"(r.y)
        : "f"(a.x), "f"(a.y), "f"(b.x), "f"(b.y));
    return r;
}
__device__ __forceinline__ float2 pkmul(float2 a, float2 b) {
    float2 r;
    asm("{\n\t.reg .b64 a64, b64, r64;\n\t"
        "mov.b64 a64, {%2, %3};\n\t"
        "mov.b64 b64, {%4, %5};\n\t"
        "mul.rn.f32x2 r64, a64, b64;\n\t"
        "mov.b64 {%0, %1}, r64;\n\t}"
        : "=f"(r.x), "=f"(r.y)
        : "f"(a.x), "f"(a.y), "f"(b.x), "f"(b.y));
    return r;
}
__device__ __forceinline__ float2 pkfma(float2 a, float2 b, float2 c) {
    float2 r;
    asm("{\n\t.reg .b64 a64, b64, c64, r64;\n\t"
        "mov.b64 a64, {%2, %3};\n\t"
        "mov.b64 b64, {%4, %5};\n\t"
        "mov.b64 c64, {%6, %7};\n\t"
        "fma.rn.f32x2 r64, a64, b64, c64;\n\t"
        "mov.b64 {%0, %1}, r64;\n\t}"
        : "=f"(r.x), "=f"(r.y)
        : "f"(a.x), "f"(a.y), "f"(b.x), "f"(b.y), "f"(c.x), "f"(c.y));
    return r;
}
__device__ __forceinline__ float2 pkbc(float v) { return make_float2(v, v); }

// ---------------- scratch (device globals: allocation-guard safe) -----------
__device__ __align__(16) float g_ax[NMAX], g_ay[NMAX], g_az[NMAX]; // ping A
__device__ __align__(16) float g_bx[NMAX], g_by[NMAX], g_bz[NMAX]; // ping B
__device__ __align__(16) float g_lam[NMAX];
__device__ __align__(16) float g_vx[NMAX], g_vy[NMAX], g_vz[NMAX];

// ---------------------------------------------------------------------------
// 1) external forces + velocity cap + predicted positions (SoA)
// ---------------------------------------------------------------------------
__global__ void k_predict(const float* __restrict__ locs,
                          const float* __restrict__ vel, int N) {
    int i = blockIdx.x * blockDim.x + threadIdx.x;
    if (i >= N) return;
    float vx = vel[3 * i + 0];
    float vy = vel[3 * i + 1] - 9.8f * DT_;
    float vz = vel[3 * i + 2];
    float nrm = sqrtf(vx * vx + vy * vy + vz * vz);
    float s = fminf(MAXV / (nrm + 1e-4f), 1.0f);
    g_ax[i] = locs[3 * i + 0] + DT_ * vx * s;
    g_ay[i] = locs[3 * i + 1] + DT_ * vy * s;
    g_az[i] = locs[3 * i + 2] + DT_ * vz * s;
}

// shared fill: SoA positions -> smem (float4 vector copies)
__device__ __forceinline__ void fill_pos(float* xs, float* ys, float* zs,
                                         const float* sx, const float* sy,
                                         const float* sz, int N) {
    for (int k = threadIdx.x; k < (N >> 2); k += blockDim.x) {
        ((float4*)xs)[k] = ((const float4*)sx)[k];
        ((float4*)ys)[k] = ((const float4*)sy)[k];
        ((float4*)zs)[k] = ((const float4*)sz)[k];
    }
    __syncthreads();
}

// ---------------------------------------------------------------------------
// 2) lambda pass: rho_i = sum_j w_ij ; lam_i = -(rho-RHO0)*STIFF
//    2 particles / warp, 2 j's / lane (f32x2), positions in SMEM
// ---------------------------------------------------------------------------
__global__ void __launch_bounds__(256, 4) k_lambda(int srcA, int N) {
    __shared__ __align__(16) float xs[NMAX], ys[NMAX], zs[NMAX];
    fill_pos(xs, ys, zs, srcA ? g_ax : g_bx, srcA ? g_ay : g_by,
             srcA ? g_az : g_bz, N);

    int w    = blockIdx.x * (blockDim.x >> 5) + (threadIdx.x >> 5);
    int lane = threadIdx.x & 31;
    int i0 = 2 * w, i1 = 2 * w + 1;
    if (i0 >= N) return;

    const float2 EPS2 = pkbc(EPS_), NEG1 = pkbc(-1.0f);
    const float2 RP = pkbc(R_), CP = pkbc(SPIKY);
    float2 px0 = pkbc(xs[i0]), py0 = pkbc(ys[i0]), pz0 = pkbc(zs[i0]);
    float2 px1 = pkbc(xs[i1]), py1 = pkbc(ys[i1]), pz1 = pkbc(zs[i1]);
    float2 r0 = make_float2(0.f, 0.f), r1 = make_float2(0.f, 0.f);

#pragma unroll 2
    for (int j = 2 * lane; j < N; j += 64) {
        float2 xj = *(const float2*)&xs[j];
        float2 yj = *(const float2*)&ys[j];
        float2 zj = *(const float2*)&zs[j];
        {   // i0
            float2 dx = pkfma(xj, NEG1, px0);
            float2 dy = pkfma(yj, NEG1, py0);
            float2 dz = pkfma(zj, NEG1, pz0);
            float2 d2 = pkfma(dx, dx, EPS2);
            d2 = pkfma(dy, dy, d2);
            d2 = pkfma(dz, dz, d2);
            float2 rv = make_float2(rsqrtf(d2.x), rsqrtf(d2.y));
            float2 d  = pkmul(d2, rv);
            float2 tp = pkfma(d, NEG1, RP);
            float2 t  = make_float2(fmaxf(tp.x, 0.f), fmaxf(tp.y, 0.f));
            float2 t2 = pkmul(t, t);
            float2 ct = pkmul(t, CP);
            r0 = pkfma(ct, t2, r0);
        }
        {   // i1
            float2 dx = pkfma(xj, NEG1, px1);
            float2 dy = pkfma(yj, NEG1, py1);
            float2 dz = pkfma(zj, NEG1, pz1);
            float2 d2 = pkfma(dx, dx, EPS2);
            d2 = pkfma(dy, dy, d2);
            d2 = pkfma(dz, dz, d2);
            float2 rv = make_float2(rsqrtf(d2.x), rsqrtf(d2.y));
            float2 d  = pkmul(d2, rv);
            float2 tp = pkfma(d, NEG1, RP);
            float2 t  = make_float2(fmaxf(tp.x, 0.f), fmaxf(tp.y, 0.f));
            float2 t2 = pkmul(t, t);
            float2 ct = pkmul(t, CP);
            r1 = pkfma(ct, t2, r1);
        }
    }
    float s0 = r0.x + r0.y, s1 = r1.x + r1.y;
#pragma unroll
    for (int o = 16; o; o >>= 1) {
        s0 += __shfl_xor_sync(0xffffffffu, s0, o);
        s1 += __shfl_xor_sync(0xffffffffu, s1, o);
    }
    if (lane == 0) {
        g_lam[i0] = -((s0 - W_SELF) - RHO0) * STIFF;
        g_lam[i1] = -((s1 - W_SELF) - RHO0) * STIFF;
    }
}

// ---------------------------------------------------------------------------
// 3) delta pass: pred_i += sum_j (lam_i+lam_j) * dw_ij / d * (p_i - p_j)
// ---------------------------------------------------------------------------
__global__ void __launch_bounds__(256, 4) k_delta(int srcA, int N) {
    __shared__ __align__(16) float xs[NMAX], ys[NMAX], zs[NMAX];
    fill_pos(xs, ys, zs, srcA ? g_ax : g_bx, srcA ? g_ay : g_by,
             srcA ? g_az : g_bz, N);
    float* dx_o = srcA ? g_bx : g_ax;
    float* dy_o = srcA ? g_by : g_ay;
    float* dz_o = srcA ? g_bz : g_az;

    int w    = blockIdx.x * (blockDim.x >> 5) + (threadIdx.x >> 5);
    int lane = threadIdx.x & 31;
    int i0 = 2 * w, i1 = 2 * w + 1;
    if (i0 >= N) return;

    const float2 EPS2 = pkbc(EPS_), NEG1 = pkbc(-1.0f);
    const float2 RP = pkbc(R_), N3P = pkbc(NSPIKY3);
    float2 px0 = pkbc(xs[i0]), py0 = pkbc(ys[i0]), pz0 = pkbc(zs[i0]);
    float2 px1 = pkbc(xs[i1]), py1 = pkbc(ys[i1]), pz1 = pkbc(zs[i1]);
    float2 li0 = pkbc(__ldg(&g_lam[i0]));
    float2 li1 = pkbc(__ldg(&g_lam[i1]));
    float2 ax0 = pkbc(0.f), ay0 = pkbc(0.f), az0 = pkbc(0.f);
    float2 ax1 = pkbc(0.f), ay1 = pkbc(0.f), az1 = pkbc(0.f);

#pragma unroll 2
    for (int j = 2 * lane; j < N; j += 64) {
        float2 xj = *(const float2*)&xs[j];
        float2 yj = *(const float2*)&ys[j];
        float2 zj = *(const float2*)&zs[j];
        float2 lj = __ldg((const float2*)&g_lam[j]);
        {   // i0
            float2 dx = pkfma(xj, NEG1, px0);
            float2 dy = pkfma(yj, NEG1, py0);
            float2 dz = pkfma(zj, NEG1, pz0);
            float2 d2 = pkfma(dx, dx, EPS2);
            d2 = pkfma(dy, dy, d2);
            d2 = pkfma(dz, dz, d2);
            float2 rv = make_float2(rsqrtf(d2.x), rsqrtf(d2.y));
            float2 d  = pkmul(d2, rv);
            float2 tp = pkfma(d, NEG1, RP);
            float2 t  = make_float2(fmaxf(tp.x, 0.f), fmaxf(tp.y, 0.f));
            float2 t2 = pkmul(t, t);
            float2 a  = pkmul(t2, N3P);
            float2 b  = pkmul(a, rv);
            float2 c  = pkmul(pkadd(li0, lj), b);
            ax0 = pkfma(c, dx, ax0);
            ay0 = pkfma(c, dy, ay0);
            az0 = pkfma(c, dz, az0);
        }
        {   // i1
            float2 dx = pkfma(xj, NEG1, px1);
            float2 dy = pkfma(yj, NEG1, py1);
            float2 dz = pkfma(zj, NEG1, pz1);
            float2 d2 = pkfma(dx, dx, EPS2);
            d2 = pkfma(dy, dy, d2);
            d2 = pkfma(dz, dz, d2);
            float2 rv = make_float2(rsqrtf(d2.x), rsqrtf(d2.y));
            float2 d  = pkmul(d2, rv);
            float2 tp = pkfma(d, NEG1, RP);
            float2 t  = make_float2(fmaxf(tp.x, 0.f), fmaxf(tp.y, 0.f));
            float2 t2 = pkmul(t, t);
            float2 a  = pkmul(t2, N3P);
            float2 b  = pkmul(a, rv);
            float2 c  = pkmul(pkadd(li1, lj), b);
            ax1 = pkfma(c, dx, ax1);
            ay1 = pkfma(c, dy, ay1);
            az1 = pkfma(c, dz, az1);
        }
    }
    float sx0 = ax0.x + ax0.y, sy0 = ay0.x + ay0.y, sz0 = az0.x + az0.y;
    float sx1 = ax1.x + ax1.y, sy1 = ay1.x + ay1.y, sz1 = az1.x + az1.y;
#pragma unroll
    for (int o = 16; o; o >>= 1) {
        sx0 += __shfl_xor_sync(0xffffffffu, sx0, o);
        sy0 += __shfl_xor_sync(0xffffffffu, sy0, o);
        sz0 += __shfl_xor_sync(0xffffffffu, sz0, o);
        sx1 += __shfl_xor_sync(0xffffffffu, sx1, o);
        sy1 += __shfl_xor_sync(0xffffffffu, sy1, o);
        sz1 += __shfl_xor_sync(0xffffffffu, sz1, o);
    }
    if (lane == 0) {
        dx_o[i0] = px0.x + sx0;  dy_o[i0] = py0.x + sy0;  dz_o[i0] = pz0.x + sz0;
        dx_o[i1] = px1.x + sx1;  dy_o[i1] = py1.x + sy1;  dz_o[i1] = pz1.x + sz1;
    }
}

// ---------------------------------------------------------------------------
// 4) new_vel = (pred - locs)/DT (SoA) ; emit pred to out
//    final pred lives in B after A->B, B->A, A->B
// ---------------------------------------------------------------------------
__global__ void k_nvout(const float* __restrict__ locs,
                        float* __restrict__ out, int N) {
    int i = blockIdx.x * blockDim.x + threadIdx.x;
    if (i >= N) return;
    float px = g_bx[i], py = g_by[i], pz = g_bz[i];
    g_vx[i] = (px - locs[3 * i + 0]) * (1.0f / DT_);
    g_vy[i] = (py - locs[3 * i + 1]) * (1.0f / DT_);
    g_vz[i] = (pz - locs[3 * i + 2]) * (1.0f / DT_);
    out[3 * i + 0] = px;
    out[3 * i + 1] = py;
    out[3 * i + 2] = pz;
}

// ---------------------------------------------------------------------------
// 5) XSPH viscosity: dv_i = sum_j w_ij (v_j - v_i); cap; emit new_vel
// ---------------------------------------------------------------------------
__global__ void __launch_bounds__(256, 4) k_xsph(float* __restrict__ out, int N) {
    __shared__ __align__(16) float xs[NMAX], ys[NMAX], zs[NMAX];
    fill_pos(xs, ys, zs, g_bx, g_by, g_bz, N);

    int w    = blockIdx.x * (blockDim.x >> 5) + (threadIdx.x >> 5);
    int lane = threadIdx.x & 31;
    int i0 = 2 * w, i1 = 2 * w + 1;
    if (i0 >= N) return;

    const float2 EPS2 = pkbc(EPS_), NEG1 = pkbc(-1.0f);
    const float2 RP = pkbc(R_), CP = pkbc(SPIKY);
    float2 px0 = pkbc(xs[i0]), py0 = pkbc(ys[i0]), pz0 = pkbc(zs[i0]);
    float2 px1 = pkbc(xs[i1]), py1 = pkbc(ys[i1]), pz1 = pkbc(zs[i1]);
    // accumulators: sum_w, sum_w*v (packed)
    float2 ws0 = pkbc(0.f), wx0 = pkbc(0.f), wy0 = pkbc(0.f), wz0 = pkbc(0.f);
    float2 ws1 = pkbc(0.f), wx1 = pkbc(0.f), wy1 = pkbc(0.f), wz1 = pkbc(0.f);

#pragma unroll 2
    for (int j = 2 * lane; j < N; j += 64) {
        float2 xj = *(const float2*)&xs[j];
        float2 yj = *(const float2*)&ys[j];
        float2 zj = *(const float2*)&zs[j];
        float2 vx = __ldg((const float2*)&g_vx[j]);
        float2 vy = __ldg((const float2*)&g_vy[j]);
        float2 vz = __ldg((const float2*)&g_vz[j]);
        {   // i0
            float2 dx = pkfma(xj, NEG1, px0);
            float2 dy = pkfma(yj, NEG1, py0);
            float2 dz = pkfma(zj, NEG1, pz0);
            float2 d2 = pkfma(dx, dx, EPS2);
            d2 = pkfma(dy, dy, d2);
            d2 = pkfma(dz, dz, d2);
            float2 rv = make_float2(rsqrtf(d2.x), rsqrtf(d2.y));
            float2 d  = pkmul(d2, rv);
            float2 tp = pkfma(d, NEG1, RP);
            float2 t  = make_float2(fmaxf(tp.x, 0.f), fmaxf(tp.y, 0.f));
            float2 wk = pkmul(pkmul(t, CP), pkmul(t, t));
            ws0 = pkadd(ws0, wk);
            wx0 = pkfma(wk, vx, wx0);
            wy0 = pkfma(wk, vy, wy0);
            wz0 = pkfma(wk, vz, wz0);
        }
        {   // i1
            float2 dx = pkfma(xj, NEG1, px1);
            float2 dy = pkfma(yj, NEG1, py1);
            float2 dz = pkfma(zj, NEG1, pz1);
            float2 d2 = pkfma(dx, dx, EPS2);
            d2 = pkfma(dy, dy, d2);
            d2 = pkfma(dz, dz, d2);
            float2 rv = make_float2(rsqrtf(d2.x), rsqrtf(d2.y));
            float2 d  = pkmul(d2, rv);
            float2 tp = pkfma(d, NEG1, RP);
            float2 t  = make_float2(fmaxf(tp.x, 0.f), fmaxf(tp.y, 0.f));
            float2 wk = pkmul(pkmul(t, CP), pkmul(t, t));
            ws1 = pkadd(ws1, wk);
            wx1 = pkfma(wk, vx, wx1);
            wy1 = pkfma(wk, vy, wy1);
            wz1 = pkfma(wk, vz, wz1);
        }
    }
    float s0 = ws0.x + ws0.y, x0 = wx0.x + wx0.y, y0 = wy0.x + wy0.y, z0 = wz0.x + wz0.y;
    float s1 = ws1.x + ws1.y, x1 = wx1.x + wx1.y, y1 = wy1.x + wy1.y, z1 = wz1.x + wz1.y;
#pragma unroll
    for (int o = 16; o; o >>= 1) {
        s0 += __shfl_xor_sync(0xffffffffu, s0, o);
        x0 += __shfl_xor_sync(0xffffffffu, x0, o);
        y0 += __shfl_xor_sync(0xffffffffu, y0, o);
        z0 += __shfl_xor_sync(0xffffffffu, z0, o);
        s1 += __shfl_xor_sync(0xffffffffu, s1, o);
        x1 += __shfl_xor_sync(0xffffffffu, x1, o);
        y1 += __shfl_xor_sync(0xffffffffu, y1, o);
        z1 += __shfl_xor_sync(0xffffffffu, z1, o);
    }
    if (lane == 0) {
        // i0
        {
            float vix = g_vx[i0], viy = g_vy[i0], viz = g_vz[i0];
            float nx = vix + VDTR * (x0 - s0 * vix);
            float ny = viy + VDTR * (y0 - s0 * viy);
            float nz = viz + VDTR * (z0 - s0 * viz);
            float nrm = sqrtf(nx * nx + ny * ny + nz * nz);
            float sc = fminf(MAXV / (nrm + 1e-4f), 1.0f);
            out[3 * N + 3 * i0 + 0] = nx * sc;
            out[3 * N + 3 * i0 + 1] = ny * sc;
            out[3 * N + 3 * i0 + 2] = nz * sc;
        }
        // i1
        {
            float vix = g_vx[i1], viy = g_vy[i1], viz = g_vz[i1];
            float nx = vix + VDTR * (x1 - s1 * vix);
            float ny = viy + VDTR * (y1 - s1 * viy);
            float nz = viz + VDTR * (z1 - s1 * viz);
            float nrm = sqrtf(nx * nx + ny * ny + nz * nz);
            float sc = fminf(MAXV / (nrm + 1e-4f), 1.0f);
            out[3 * N + 3 * i1 + 0] = nx * sc;
            out[3 * N + 3 * i1 + 1] = ny * sc;
            out[3 * N + 3 * i1 + 2] = nz * sc;
        }
    }
}

// ---------------------------------------------------------------------------
extern "C" void kernel_launch(void* const* d_in, const int* in_sizes, int n_in,
                              void* d_out, int out_size) {
    const float* locs = (const float*)d_in[0];
    const float* vel  = (const float*)d_in[1];
    float* out = (float*)d_out;
    int N = in_sizes[0] / 3;  // 4096

    const int TPB = 256;
    int eb = (N + TPB - 1) / TPB;               // elementwise blocks
    // warp-per-2-particles: N/2 warps, 8 warps/block
    int pb = (N / 2 + (TPB / 32) - 1) / (TPB / 32);

    k_predict<<<eb, TPB>>>(locs, vel, N);
    int srcA = 1;
    for (int it = 0; it < 3; ++it) {
        k_lambda<<<pb, TPB>>>(srcA, N);
        k_delta<<<pb, TPB>>>(srcA, N);
        srcA ^= 1;
    }
    k_nvout<<<eb, TPB>>>(locs, out, N);
    k_xsph<<<pb, TPB>>>(out, N);
}